// round 4
// baseline (speedup 1.0000x reference)
#include <cuda_runtime.h>
#include <math.h>

#define NN 100000
#define EE 1600000
#define SCAN_B 1024
#define NBLK ((NN + SCAN_B - 1) / SCAN_B)   // 98

// ---------------- scratch (no allocations allowed) ----------------
__device__ __align__(16) float g_dinv[NN];
__device__ __align__(16) int   g_degi[NN];
__device__ __align__(16) int   g_rowstart[NN + 1];
__device__ __align__(16) int   g_cursor[NN];
__device__ __align__(16) int   g_bsum[256];
__device__ __align__(16) int   g_bsum2[256];
__device__ __align__(16) int   g_esrc[EE];
__device__ __align__(16) float g_xw[(size_t)NN * 128];   // x @ W1
__device__ __align__(16) float g_h[(size_t)NN * 128];    // relu(aggregated layer 1)
__device__ __align__(16) float g_hw2[(size_t)NN * 40];   // relu(h) @ W2

// ---------------- degree histogram ----------------
__global__ void k_zero_deg() {
    int i = blockIdx.x * blockDim.x + threadIdx.x;
    if (i < NN) g_degi[i] = 0;
}

__global__ void k_hist(const int* __restrict__ ei) {
    int e = blockIdx.x * blockDim.x + threadIdx.x;
    if (e < EE) atomicAdd(&g_degi[ei[EE + e]], 1);
}

__global__ void k_dinv() {
    int i = blockIdx.x * blockDim.x + threadIdx.x;
    if (i < NN) g_dinv[i] = rsqrtf((float)(g_degi[i] + 1));  // +1 self loop
}

// ---------------- prefix scan (exclusive) of g_degi -> g_rowstart ----------------
__global__ void k_scan1() {
    __shared__ int sh[SCAN_B];
    int i = blockIdx.x * SCAN_B + threadIdx.x;
    int v = (i < NN) ? g_degi[i] : 0;
    sh[threadIdx.x] = v;
    __syncthreads();
    for (int o = 1; o < SCAN_B; o <<= 1) {
        int t = (threadIdx.x >= o) ? sh[threadIdx.x - o] : 0;
        __syncthreads();
        sh[threadIdx.x] += t;
        __syncthreads();
    }
    if (threadIdx.x == SCAN_B - 1) g_bsum[blockIdx.x] = sh[SCAN_B - 1];
    if (i < NN) g_rowstart[i] = sh[threadIdx.x] - v;   // exclusive
}

__global__ void k_scan2() {
    __shared__ int sh[128];
    int v = (threadIdx.x < NBLK) ? g_bsum[threadIdx.x] : 0;
    sh[threadIdx.x] = v;
    __syncthreads();
    for (int o = 1; o < 128; o <<= 1) {
        int t = (threadIdx.x >= o) ? sh[threadIdx.x - o] : 0;
        __syncthreads();
        sh[threadIdx.x] += t;
        __syncthreads();
    }
    g_bsum2[threadIdx.x] = sh[threadIdx.x] - v;        // exclusive
}

__global__ void k_scan3() {
    int i = blockIdx.x * blockDim.x + threadIdx.x;
    if (i < NN) {
        int r = g_rowstart[i] + g_bsum2[i / SCAN_B];
        g_rowstart[i] = r;
        g_cursor[i] = r;
    }
    if (i == 0) g_rowstart[NN] = EE;
}

// ---------------- counting-sort fill: CSR over dst ----------------
__global__ void k_fill(const int* __restrict__ ei) {
    int e = blockIdx.x * blockDim.x + threadIdx.x;
    if (e < EE) {
        int s = ei[e];
        int d = ei[EE + e];
        int pos = atomicAdd(&g_cursor[d], 1);
        g_esrc[pos] = s;
    }
}

// ---------------- GEMM1: g_xw = x[N,256] @ W1[256,128] ----------------
__global__ void __launch_bounds__(256) k_gemm1(const float* __restrict__ A,
                                               const float* __restrict__ B) {
    __shared__ float As[8][132];
    __shared__ float Bs[8][128];
    const int tid = threadIdx.x;
    const int block_row = blockIdx.x * 128;
    const int tm = (tid >> 4) * 8;
    const int tn = (tid & 15) * 8;

    float acc[8][8];
#pragma unroll
    for (int i = 0; i < 8; i++)
#pragma unroll
        for (int j = 0; j < 8; j++) acc[i][j] = 0.f;

    for (int k0 = 0; k0 < 256; k0 += 8) {
#pragma unroll
        for (int i = 0; i < 4; i++) {
            int idx = tid + i * 256;
            int m  = idx >> 3;
            int kk = idx & 7;
            int row = block_row + m;
            As[kk][m] = (row < NN) ? A[(size_t)row * 256 + k0 + kk] : 0.f;
        }
#pragma unroll
        for (int i = 0; i < 4; i++) {
            int idx = tid + i * 256;
            int kk = idx >> 7;
            int n  = idx & 127;
            Bs[kk][n] = B[(size_t)(k0 + kk) * 128 + n];
        }
        __syncthreads();
#pragma unroll
        for (int kk = 0; kk < 8; kk++) {
            float a[8], b[8];
            *(float4*)&a[0] = *(const float4*)&As[kk][tm];
            *(float4*)&a[4] = *(const float4*)&As[kk][tm + 4];
            *(float4*)&b[0] = *(const float4*)&Bs[kk][tn];
            *(float4*)&b[4] = *(const float4*)&Bs[kk][tn + 4];
#pragma unroll
            for (int i = 0; i < 8; i++)
#pragma unroll
                for (int j = 0; j < 8; j++) acc[i][j] += a[i] * b[j];
        }
        __syncthreads();
    }
#pragma unroll
    for (int i = 0; i < 8; i++) {
        int row = block_row + tm + i;
        if (row < NN) {
            *(float4*)&g_xw[(size_t)row * 128 + tn]     = *(float4*)&acc[i][0];
            *(float4*)&g_xw[(size_t)row * 128 + tn + 4] = *(float4*)&acc[i][4];
        }
    }
}

// ---------------- aggregation layer 1: warp per node, no atomics ----------------
// g_h[node] = relu( sum_{s in N(node)} dinv[s]*dinv[node]*xw[s] + dinv[node]^2*xw[node] + b1 )
__global__ void __launch_bounds__(256) k_agg1(const float* __restrict__ b1) {
    int node = blockIdx.x * 8 + (threadIdx.x >> 5);
    int lane = threadIdx.x & 31;
    if (node >= NN) return;
    int beg = g_rowstart[node];
    int end = g_rowstart[node + 1];
    float dd = g_dinv[node];

    float4 acc = make_float4(0.f, 0.f, 0.f, 0.f);
    for (int i = beg; i < end; i++) {
        int s = g_esrc[i];
        float nrm = dd * g_dinv[s];
        float4 v = *(const float4*)&g_xw[(size_t)s * 128 + lane * 4];
        acc.x += v.x * nrm; acc.y += v.y * nrm;
        acc.z += v.z * nrm; acc.w += v.w * nrm;
    }
    float self = dd * dd;
    float4 sv = *(const float4*)&g_xw[(size_t)node * 128 + lane * 4];
    float4 bb = *(const float4*)&b1[lane * 4];
    acc.x = fmaxf(acc.x + sv.x * self + bb.x, 0.f);
    acc.y = fmaxf(acc.y + sv.y * self + bb.y, 0.f);
    acc.z = fmaxf(acc.z + sv.z * self + bb.z, 0.f);
    acc.w = fmaxf(acc.w + sv.w * self + bb.w, 0.f);
    *(float4*)&g_h[(size_t)node * 128 + lane * 4] = acc;
}

// ---------------- GEMM2: g_hw2 = g_h[N,128] @ W2[128,40] ----------------
__global__ void __launch_bounds__(256) k_gemm2(const float* __restrict__ B) {
    __shared__ float As[16][133];
    __shared__ float Bs[16][40];
    const int tid = threadIdx.x;
    const int block_row = blockIdx.x * 128;
    const int tr = (tid >> 3) * 4;
    const int tc = (tid & 7) * 5;

    float acc[4][5];
#pragma unroll
    for (int i = 0; i < 4; i++)
#pragma unroll
        for (int j = 0; j < 5; j++) acc[i][j] = 0.f;

    for (int k0 = 0; k0 < 128; k0 += 16) {
#pragma unroll
        for (int i = 0; i < 8; i++) {
            int idx = tid + i * 256;
            int m  = idx >> 4;
            int kk = idx & 15;
            int row = block_row + m;
            As[kk][m] = (row < NN) ? g_h[(size_t)row * 128 + k0 + kk] : 0.f;
        }
        for (int idx = tid; idx < 640; idx += 256) {
            int kk = idx / 40;
            int n  = idx % 40;
            Bs[kk][n] = B[(k0 + kk) * 40 + n];
        }
        __syncthreads();
#pragma unroll
        for (int kk = 0; kk < 16; kk++) {
            float a[4], b[5];
#pragma unroll
            for (int i = 0; i < 4; i++) a[i] = As[kk][tr + i];
#pragma unroll
            for (int j = 0; j < 5; j++) b[j] = Bs[kk][tc + j];
#pragma unroll
            for (int i = 0; i < 4; i++)
#pragma unroll
                for (int j = 0; j < 5; j++) acc[i][j] += a[i] * b[j];
        }
        __syncthreads();
    }
#pragma unroll
    for (int i = 0; i < 4; i++) {
        int row = block_row + tr + i;
        if (row < NN) {
#pragma unroll
            for (int j = 0; j < 5; j++) g_hw2[(size_t)row * 40 + tc + j] = acc[i][j];
        }
    }
}

// ---------------- aggregation layer 2 + bias + log_softmax, warp per node ----------------
__global__ void __launch_bounds__(256) k_agg2(const float* __restrict__ b2,
                                              float* __restrict__ out) {
    int node = blockIdx.x * 8 + (threadIdx.x >> 5);
    int lane = threadIdx.x & 31;
    if (node >= NN) return;
    int beg = g_rowstart[node];
    int end = g_rowstart[node + 1];
    float dd = g_dinv[node];
    bool active = lane < 10;   // 10 float4 chunks cover 40 cols

    float4 acc = make_float4(0.f, 0.f, 0.f, 0.f);
    for (int i = beg; i < end; i++) {
        int s = g_esrc[i];
        float nrm = dd * g_dinv[s];
        if (active) {
            float4 v = *(const float4*)&g_hw2[(size_t)s * 40 + lane * 4];
            acc.x += v.x * nrm; acc.y += v.y * nrm;
            acc.z += v.z * nrm; acc.w += v.w * nrm;
        }
    }
    if (active) {
        float self = dd * dd;
        float4 sv = *(const float4*)&g_hw2[(size_t)node * 40 + lane * 4];
        float4 bb = *(const float4*)&b2[lane * 4];
        acc.x += sv.x * self + bb.x;
        acc.y += sv.y * self + bb.y;
        acc.z += sv.z * self + bb.z;
        acc.w += sv.w * self + bb.w;
    }

    // log_softmax across 40 values spread over lanes 0..9 (x4)
    float m = active ? fmaxf(fmaxf(acc.x, acc.y), fmaxf(acc.z, acc.w)) : -INFINITY;
#pragma unroll
    for (int o = 16; o > 0; o >>= 1) m = fmaxf(m, __shfl_xor_sync(0xffffffffu, m, o));
    float s = active ? (expf(acc.x - m) + expf(acc.y - m) +
                        expf(acc.z - m) + expf(acc.w - m)) : 0.f;
#pragma unroll
    for (int o = 16; o > 0; o >>= 1) s += __shfl_xor_sync(0xffffffffu, s, o);
    float L = m + logf(s);

    if (active) {
        float4 o4;
        o4.x = acc.x - L; o4.y = acc.y - L;
        o4.z = acc.z - L; o4.w = acc.w - L;
        *(float4*)&out[(size_t)node * 40 + lane * 4] = o4;
    }
}

// ---------------- launch ----------------
extern "C" void kernel_launch(void* const* d_in, const int* in_sizes, int n_in,
                              void* d_out, int out_size) {
    const float* x  = (const float*)d_in[0];
    const int*   ei = (const int*)d_in[1];     // int32! (JAX default x64-disabled)
    const float* W1 = (const float*)d_in[2];
    const float* b1 = (const float*)d_in[3];
    const float* W2 = (const float*)d_in[4];
    const float* b2 = (const float*)d_in[5];
    float* out = (float*)d_out;

    k_zero_deg<<<(NN + 255) / 256, 256>>>();
    k_hist<<<(EE + 255) / 256, 256>>>(ei);
    k_dinv<<<(NN + 255) / 256, 256>>>();

    k_scan1<<<NBLK, SCAN_B>>>();
    k_scan2<<<1, 128>>>();
    k_scan3<<<(NN + 255) / 256, 256>>>();
    k_fill<<<(EE + 255) / 256, 256>>>(ei);

    k_gemm1<<<(NN + 127) / 128, 256>>>(x, W1);
    k_agg1<<<(NN + 7) / 8, 256>>>(b1);

    k_gemm2<<<(NN + 127) / 128, 256>>>(W2);
    k_agg2<<<(NN + 7) / 8, 256>>>(b2, out);
}

// round 5
// speedup vs baseline: 1.3601x; 1.3601x over previous
#include <cuda_runtime.h>
#include <math.h>

#define NN 100000
#define EE 1600000
#define SCAN_B 1024
#define NBLK ((NN + SCAN_B - 1) / SCAN_B)   // 98

// ---------------- scratch (no allocations allowed) ----------------
__device__ __align__(16) float g_dinv[NN];
__device__ __align__(16) int   g_degi[NN];
__device__ __align__(16) int   g_rowstart[NN + 1];
__device__ __align__(16) int   g_cursor[NN];
__device__ __align__(16) int   g_bsum[256];
__device__ __align__(16) int   g_bsum2[256];
__device__ __align__(16) int   g_esrc[EE];
__device__ __align__(16) float g_xw[(size_t)NN * 128];   // x @ W1
__device__ __align__(16) float g_h[(size_t)NN * 128];    // relu(aggregated layer 1)
__device__ __align__(16) float g_hw2[(size_t)NN * 40];   // relu(h) @ W2

// ---------------- degree histogram ----------------
__global__ void k_zero_deg() {
    int i = blockIdx.x * blockDim.x + threadIdx.x;
    if (i < NN) g_degi[i] = 0;
}

__global__ void k_hist(const int* __restrict__ ei) {
    int e = blockIdx.x * blockDim.x + threadIdx.x;
    if (e < EE) atomicAdd(&g_degi[ei[EE + e]], 1);
}

__global__ void k_dinv() {
    int i = blockIdx.x * blockDim.x + threadIdx.x;
    if (i < NN) g_dinv[i] = rsqrtf((float)(g_degi[i] + 1));  // +1 self loop
}

// ---------------- prefix scan (exclusive) of g_degi -> g_rowstart ----------------
__global__ void k_scan1() {
    __shared__ int sh[SCAN_B];
    int i = blockIdx.x * SCAN_B + threadIdx.x;
    int v = (i < NN) ? g_degi[i] : 0;
    sh[threadIdx.x] = v;
    __syncthreads();
    for (int o = 1; o < SCAN_B; o <<= 1) {
        int t = (threadIdx.x >= o) ? sh[threadIdx.x - o] : 0;
        __syncthreads();
        sh[threadIdx.x] += t;
        __syncthreads();
    }
    if (threadIdx.x == SCAN_B - 1) g_bsum[blockIdx.x] = sh[SCAN_B - 1];
    if (i < NN) g_rowstart[i] = sh[threadIdx.x] - v;   // exclusive
}

__global__ void k_scan2() {
    __shared__ int sh[128];
    int v = (threadIdx.x < NBLK) ? g_bsum[threadIdx.x] : 0;
    sh[threadIdx.x] = v;
    __syncthreads();
    for (int o = 1; o < 128; o <<= 1) {
        int t = (threadIdx.x >= o) ? sh[threadIdx.x - o] : 0;
        __syncthreads();
        sh[threadIdx.x] += t;
        __syncthreads();
    }
    g_bsum2[threadIdx.x] = sh[threadIdx.x] - v;        // exclusive
}

__global__ void k_scan3() {
    int i = blockIdx.x * blockDim.x + threadIdx.x;
    if (i < NN) {
        int r = g_rowstart[i] + g_bsum2[i / SCAN_B];
        g_rowstart[i] = r;
        g_cursor[i] = r;
    }
    if (i == 0) g_rowstart[NN] = EE;
}

// ---------------- counting-sort fill: CSR over dst ----------------
__global__ void k_fill(const int* __restrict__ ei) {
    int e = blockIdx.x * blockDim.x + threadIdx.x;
    if (e < EE) {
        int s = ei[e];
        int d = ei[EE + e];
        int pos = atomicAdd(&g_cursor[d], 1);
        g_esrc[pos] = s;
    }
}

// ---------------- helpers for tf32 mma ----------------
__device__ __forceinline__ float to_tf32(float x) {
    unsigned r;
    asm("cvt.rna.tf32.f32 %0, %1;" : "=r"(r) : "f"(x));
    return __uint_as_float(r);
}

__device__ __forceinline__ void mma_tf32(float* d, const unsigned* a, const unsigned* b) {
    asm volatile(
        "mma.sync.aligned.m16n8k8.row.col.f32.tf32.tf32.f32 "
        "{%0,%1,%2,%3}, {%4,%5,%6,%7}, {%8,%9}, {%0,%1,%2,%3};"
        : "+f"(d[0]), "+f"(d[1]), "+f"(d[2]), "+f"(d[3])
        : "r"(a[0]), "r"(a[1]), "r"(a[2]), "r"(a[3]),
          "r"(b[0]), "r"(b[1]));
}

// ---------------- GEMM1 (tf32 tensor): g_xw = x[N,256] @ W1[256,128] ----------------
// 128x128 block, 8 warps (2M x 4N), warp tile 64x32, k-chunk 32.
__global__ void __launch_bounds__(256) k_gemm1(const float* __restrict__ A,
                                               const float* __restrict__ B) {
    __shared__ float As[32][132];   // [k][m], conflict-free fragment loads
    __shared__ float Bs[32][132];   // [k][n]
    const int tid   = threadIdx.x;
    const int lane  = tid & 31;
    const int gid   = lane >> 2;    // 0..7
    const int tig   = lane & 3;     // 0..3
    const int warpM = (tid >> 5) & 1;
    const int warpN = (tid >> 6);   // 0..3
    const int blockRow = blockIdx.x * 128;

    float acc[4][4][4];
#pragma unroll
    for (int mt = 0; mt < 4; mt++)
#pragma unroll
        for (int nt = 0; nt < 4; nt++)
#pragma unroll
            for (int r = 0; r < 4; r++) acc[mt][nt][r] = 0.f;

    for (int k0 = 0; k0 < 256; k0 += 32) {
        // load A chunk 128x32 (row-major gmem) -> As[k][m]
#pragma unroll
        for (int i = 0; i < 4; i++) {
            int idx = tid + i * 256;        // 0..1023
            int m   = idx >> 3;             // 0..127
            int k4  = (idx & 7) * 4;        // 0,4,..,28
            int row = blockRow + m;
            float4 v = make_float4(0.f, 0.f, 0.f, 0.f);
            if (row < NN) v = *(const float4*)&A[(size_t)row * 256 + k0 + k4];
            As[k4 + 0][m] = to_tf32(v.x);
            As[k4 + 1][m] = to_tf32(v.y);
            As[k4 + 2][m] = to_tf32(v.z);
            As[k4 + 3][m] = to_tf32(v.w);
        }
        // load B chunk 32x128 -> Bs[k][n]
#pragma unroll
        for (int i = 0; i < 4; i++) {
            int idx = tid + i * 256;
            int kk  = idx >> 5;             // 0..31
            int n4  = (idx & 31) * 4;       // 0..124
            float4 v = *(const float4*)&B[(size_t)(k0 + kk) * 128 + n4];
            Bs[kk][n4 + 0] = to_tf32(v.x);
            Bs[kk][n4 + 1] = to_tf32(v.y);
            Bs[kk][n4 + 2] = to_tf32(v.z);
            Bs[kk][n4 + 3] = to_tf32(v.w);
        }
        __syncthreads();

#pragma unroll
        for (int ks = 0; ks < 4; ks++) {
            unsigned a[4][4], b[4][2];
#pragma unroll
            for (int mt = 0; mt < 4; mt++) {
                int r = warpM * 64 + mt * 16 + gid;
                int k = ks * 8 + tig;
                a[mt][0] = __float_as_uint(As[k][r]);
                a[mt][1] = __float_as_uint(As[k][r + 8]);
                a[mt][2] = __float_as_uint(As[k + 4][r]);
                a[mt][3] = __float_as_uint(As[k + 4][r + 8]);
            }
#pragma unroll
            for (int nt = 0; nt < 4; nt++) {
                int c = warpN * 32 + nt * 8 + gid;
                int k = ks * 8 + tig;
                b[nt][0] = __float_as_uint(Bs[k][c]);
                b[nt][1] = __float_as_uint(Bs[k + 4][c]);
            }
#pragma unroll
            for (int mt = 0; mt < 4; mt++)
#pragma unroll
                for (int nt = 0; nt < 4; nt++)
                    mma_tf32(acc[mt][nt], a[mt], b[nt]);
        }
        __syncthreads();
    }

    // store: c0,c1 -> (row, 2*tig..+1), c2,c3 -> (row+8, ...)
#pragma unroll
    for (int mt = 0; mt < 4; mt++) {
        int r0 = blockRow + warpM * 64 + mt * 16 + gid;
#pragma unroll
        for (int nt = 0; nt < 4; nt++) {
            int c = warpN * 32 + nt * 8 + tig * 2;
            if (r0 < NN)
                *(float2*)&g_xw[(size_t)r0 * 128 + c] = make_float2(acc[mt][nt][0], acc[mt][nt][1]);
            if (r0 + 8 < NN)
                *(float2*)&g_xw[(size_t)(r0 + 8) * 128 + c] = make_float2(acc[mt][nt][2], acc[mt][nt][3]);
        }
    }
}

// ---------------- aggregation layer 1: warp per node, no atomics ----------------
__global__ void __launch_bounds__(256) k_agg1(const float* __restrict__ b1) {
    int node = blockIdx.x * 8 + (threadIdx.x >> 5);
    int lane = threadIdx.x & 31;
    if (node >= NN) return;
    int beg = g_rowstart[node];
    int end = g_rowstart[node + 1];
    float dd = g_dinv[node];

    float4 acc = make_float4(0.f, 0.f, 0.f, 0.f);
    for (int i = beg; i < end; i++) {
        int s = g_esrc[i];
        float nrm = dd * g_dinv[s];
        float4 v = *(const float4*)&g_xw[(size_t)s * 128 + lane * 4];
        acc.x += v.x * nrm; acc.y += v.y * nrm;
        acc.z += v.z * nrm; acc.w += v.w * nrm;
    }
    float self = dd * dd;
    float4 sv = *(const float4*)&g_xw[(size_t)node * 128 + lane * 4];
    float4 bb = *(const float4*)&b1[lane * 4];
    acc.x = fmaxf(acc.x + sv.x * self + bb.x, 0.f);
    acc.y = fmaxf(acc.y + sv.y * self + bb.y, 0.f);
    acc.z = fmaxf(acc.z + sv.z * self + bb.z, 0.f);
    acc.w = fmaxf(acc.w + sv.w * self + bb.w, 0.f);
    *(float4*)&g_h[(size_t)node * 128 + lane * 4] = acc;
}

// ---------------- GEMM2: g_hw2 = g_h[N,128] @ W2[128,40] ----------------
__global__ void __launch_bounds__(256) k_gemm2(const float* __restrict__ B) {
    __shared__ float As[16][133];
    __shared__ float Bs[16][40];
    const int tid = threadIdx.x;
    const int block_row = blockIdx.x * 128;
    const int tr = (tid >> 3) * 4;
    const int tc = (tid & 7) * 5;

    float acc[4][5];
#pragma unroll
    for (int i = 0; i < 4; i++)
#pragma unroll
        for (int j = 0; j < 5; j++) acc[i][j] = 0.f;

    for (int k0 = 0; k0 < 128; k0 += 16) {
#pragma unroll
        for (int i = 0; i < 8; i++) {
            int idx = tid + i * 256;
            int m  = idx >> 4;
            int kk = idx & 15;
            int row = block_row + m;
            As[kk][m] = (row < NN) ? g_h[(size_t)row * 128 + k0 + kk] : 0.f;
        }
        for (int idx = tid; idx < 640; idx += 256) {
            int kk = idx / 40;
            int n  = idx % 40;
            Bs[kk][n] = B[(k0 + kk) * 40 + n];
        }
        __syncthreads();
#pragma unroll
        for (int kk = 0; kk < 16; kk++) {
            float a[4], b[5];
#pragma unroll
            for (int i = 0; i < 4; i++) a[i] = As[kk][tr + i];
#pragma unroll
            for (int j = 0; j < 5; j++) b[j] = Bs[kk][tc + j];
#pragma unroll
            for (int i = 0; i < 4; i++)
#pragma unroll
                for (int j = 0; j < 5; j++) acc[i][j] += a[i] * b[j];
        }
        __syncthreads();
    }
#pragma unroll
    for (int i = 0; i < 4; i++) {
        int row = block_row + tr + i;
        if (row < NN) {
#pragma unroll
            for (int j = 0; j < 5; j++) g_hw2[(size_t)row * 40 + tc + j] = acc[i][j];
        }
    }
}

// ---------------- aggregation layer 2 + bias + log_softmax, warp per node ----------------
__global__ void __launch_bounds__(256) k_agg2(const float* __restrict__ b2,
                                              float* __restrict__ out) {
    int node = blockIdx.x * 8 + (threadIdx.x >> 5);
    int lane = threadIdx.x & 31;
    if (node >= NN) return;
    int beg = g_rowstart[node];
    int end = g_rowstart[node + 1];
    float dd = g_dinv[node];
    bool active = lane < 10;   // 10 float4 chunks cover 40 cols

    float4 acc = make_float4(0.f, 0.f, 0.f, 0.f);
    for (int i = beg; i < end; i++) {
        int s = g_esrc[i];
        float nrm = dd * g_dinv[s];
        if (active) {
            float4 v = *(const float4*)&g_hw2[(size_t)s * 40 + lane * 4];
            acc.x += v.x * nrm; acc.y += v.y * nrm;
            acc.z += v.z * nrm; acc.w += v.w * nrm;
        }
    }
    if (active) {
        float self = dd * dd;
        float4 sv = *(const float4*)&g_hw2[(size_t)node * 40 + lane * 4];
        float4 bb = *(const float4*)&b2[lane * 4];
        acc.x += sv.x * self + bb.x;
        acc.y += sv.y * self + bb.y;
        acc.z += sv.z * self + bb.z;
        acc.w += sv.w * self + bb.w;
    }

    float m = active ? fmaxf(fmaxf(acc.x, acc.y), fmaxf(acc.z, acc.w)) : -INFINITY;
#pragma unroll
    for (int o = 16; o > 0; o >>= 1) m = fmaxf(m, __shfl_xor_sync(0xffffffffu, m, o));
    float s = active ? (expf(acc.x - m) + expf(acc.y - m) +
                        expf(acc.z - m) + expf(acc.w - m)) : 0.f;
#pragma unroll
    for (int o = 16; o > 0; o >>= 1) s += __shfl_xor_sync(0xffffffffu, s, o);
    float L = m + logf(s);

    if (active) {
        float4 o4;
        o4.x = acc.x - L; o4.y = acc.y - L;
        o4.z = acc.z - L; o4.w = acc.w - L;
        *(float4*)&out[(size_t)node * 40 + lane * 4] = o4;
    }
}

// ---------------- launch ----------------
extern "C" void kernel_launch(void* const* d_in, const int* in_sizes, int n_in,
                              void* d_out, int out_size) {
    const float* x  = (const float*)d_in[0];
    const int*   ei = (const int*)d_in[1];     // int32 (JAX x64 disabled)
    const float* W1 = (const float*)d_in[2];
    const float* b1 = (const float*)d_in[3];
    const float* W2 = (const float*)d_in[4];
    const float* b2 = (const float*)d_in[5];
    float* out = (float*)d_out;

    k_zero_deg<<<(NN + 255) / 256, 256>>>();
    k_hist<<<(EE + 255) / 256, 256>>>(ei);
    k_dinv<<<(NN + 255) / 256, 256>>>();

    k_scan1<<<NBLK, SCAN_B>>>();
    k_scan2<<<1, 128>>>();
    k_scan3<<<(NN + 255) / 256, 256>>>();
    k_fill<<<(EE + 255) / 256, 256>>>(ei);

    k_gemm1<<<(NN + 127) / 128, 256>>>(x, W1);
    k_agg1<<<(NN + 7) / 8, 256>>>(b1);

    k_gemm2<<<(NN + 127) / 128, 256>>>(W2);
    k_agg2<<<(NN + 7) / 8, 256>>>(b2, out);
}

// round 6
// speedup vs baseline: 1.4784x; 1.0870x over previous
#include <cuda_runtime.h>
#include <cuda_fp16.h>
#include <math.h>

#define NN 100000
#define EE 1600000
#define SCAN_B 1024
#define NBLK ((NN + SCAN_B - 1) / SCAN_B)   // 98

// ---------------- scratch (no allocations allowed) ----------------
__device__ __align__(16) float  g_dinv[NN];
__device__ __align__(16) int    g_degi[NN];
__device__ __align__(16) int    g_rowstart[NN + 1];
__device__ __align__(16) int    g_cursor[NN];
__device__ __align__(16) int    g_bsum[256];
__device__ __align__(16) int    g_bsum2[256];
__device__ __align__(16) int    g_esrc[EE];
__device__ __align__(16) __half g_xw_h[(size_t)NN * 128]; // x @ W1 (fp16)
__device__ __align__(16) float  g_h[(size_t)NN * 128];    // relu(aggregated layer 1)
__device__ __align__(16) float  g_hw2[(size_t)NN * 40];   // relu(h) @ W2

// ---------------- degree histogram ----------------
__global__ void k_zero_deg() {
    int i = blockIdx.x * blockDim.x + threadIdx.x;
    if (i < NN) g_degi[i] = 0;
}

__global__ void k_hist(const int* __restrict__ ei) {
    int e = blockIdx.x * blockDim.x + threadIdx.x;
    if (e < EE) atomicAdd(&g_degi[ei[EE + e]], 1);
}

__global__ void k_dinv() {
    int i = blockIdx.x * blockDim.x + threadIdx.x;
    if (i < NN) g_dinv[i] = rsqrtf((float)(g_degi[i] + 1));  // +1 self loop
}

// ---------------- prefix scan (exclusive) of g_degi -> g_rowstart ----------------
__global__ void k_scan1() {
    __shared__ int sh[SCAN_B];
    int i = blockIdx.x * SCAN_B + threadIdx.x;
    int v = (i < NN) ? g_degi[i] : 0;
    sh[threadIdx.x] = v;
    __syncthreads();
    for (int o = 1; o < SCAN_B; o <<= 1) {
        int t = (threadIdx.x >= o) ? sh[threadIdx.x - o] : 0;
        __syncthreads();
        sh[threadIdx.x] += t;
        __syncthreads();
    }
    if (threadIdx.x == SCAN_B - 1) g_bsum[blockIdx.x] = sh[SCAN_B - 1];
    if (i < NN) g_rowstart[i] = sh[threadIdx.x] - v;   // exclusive
}

__global__ void k_scan2() {
    __shared__ int sh[128];
    int v = (threadIdx.x < NBLK) ? g_bsum[threadIdx.x] : 0;
    sh[threadIdx.x] = v;
    __syncthreads();
    for (int o = 1; o < 128; o <<= 1) {
        int t = (threadIdx.x >= o) ? sh[threadIdx.x - o] : 0;
        __syncthreads();
        sh[threadIdx.x] += t;
        __syncthreads();
    }
    g_bsum2[threadIdx.x] = sh[threadIdx.x] - v;        // exclusive
}

__global__ void k_scan3() {
    int i = blockIdx.x * blockDim.x + threadIdx.x;
    if (i < NN) {
        int r = g_rowstart[i] + g_bsum2[i / SCAN_B];
        g_rowstart[i] = r;
        g_cursor[i] = r;
    }
    if (i == 0) g_rowstart[NN] = EE;
}

// ---------------- counting-sort fill: CSR over dst ----------------
__global__ void k_fill(const int* __restrict__ ei) {
    int e = blockIdx.x * blockDim.x + threadIdx.x;
    if (e < EE) {
        int s = ei[e];
        int d = ei[EE + e];
        int pos = atomicAdd(&g_cursor[d], 1);
        g_esrc[pos] = s;
    }
}

// ---------------- tf32 mma + cp.async helpers ----------------
__device__ __forceinline__ void mma_tf32(float* d, const unsigned* a, const unsigned* b) {
    asm volatile(
        "mma.sync.aligned.m16n8k8.row.col.f32.tf32.tf32.f32 "
        "{%0,%1,%2,%3}, {%4,%5,%6,%7}, {%8,%9}, {%0,%1,%2,%3};"
        : "+f"(d[0]), "+f"(d[1]), "+f"(d[2]), "+f"(d[3])
        : "r"(a[0]), "r"(a[1]), "r"(a[2]), "r"(a[3]),
          "r"(b[0]), "r"(b[1]));
}

__device__ __forceinline__ void cp16(void* dst, const void* src, int src_bytes) {
    unsigned d = (unsigned)__cvta_generic_to_shared(dst);
    asm volatile("cp.async.cg.shared.global [%0], [%1], 16, %2;"
                 :: "r"(d), "l"(src), "r"(src_bytes));
}
__device__ __forceinline__ void cp_commit() { asm volatile("cp.async.commit_group;"); }
__device__ __forceinline__ void cp_wait1()  { asm volatile("cp.async.wait_group 1;"); }
__device__ __forceinline__ void cp_wait0()  { asm volatile("cp.async.wait_group 0;"); }

// ---------------- GEMM1 (tf32, double-buffered cp.async) ----------------
// g_xw_h = fp16( x[N,256] @ W1[256,128] ).  128x128 block, 8 warps (2Mx4N), BK=16.
__global__ void __launch_bounds__(256) k_gemm1(const float* __restrict__ A,
                                               const float* __restrict__ B) {
    __shared__ float As[2][128][20];   // [m][k], stride 20 -> conflict-free frags
    __shared__ float Bs[2][16][132];   // [k][n]
    const int tid   = threadIdx.x;
    const int lane  = tid & 31;
    const int gid   = lane >> 2;    // 0..7
    const int tig   = lane & 3;     // 0..3
    const int warpM = (tid >> 5) & 1;
    const int warpN = (tid >> 6);   // 0..3
    const int blockRow = blockIdx.x * 128;

    float acc[4][4][4];
#pragma unroll
    for (int mt = 0; mt < 4; mt++)
#pragma unroll
        for (int nt = 0; nt < 4; nt++)
#pragma unroll
            for (int r = 0; r < 4; r++) acc[mt][nt][r] = 0.f;

    // per-thread load coords (2 x 16B chunks of A, 2 x 16B chunks of B)
    const int ar0 = tid >> 1,           ak0 = (tid & 1) * 8;       // chunk pair: k offsets ak0, ak0+4
    const int bk0 = tid >> 4,           bn0 = (tid & 15) * 8;      // 16 rows x 128 cols

    auto load_stage = [&](int st, int k0) {
        // A: 128 rows x 16 k
        int row = blockRow + ar0;
        int ok  = (row < NN) ? 16 : 0;
        const float* src = &A[(size_t)row * 256 + k0 + ak0];
        cp16(&As[st][ar0][ak0],     src,     ok);
        cp16(&As[st][ar0][ak0 + 4], src + 4, ok);
        // B: 16 k x 128 n
        const float* bs = &B[(size_t)(k0 + bk0) * 128 + bn0];
        cp16(&Bs[st][bk0][bn0],     bs,     16);
        cp16(&Bs[st][bk0][bn0 + 4], bs + 4, 16);
        cp_commit();
    };

    load_stage(0, 0);

    for (int it = 0; it < 16; it++) {
        int st = it & 1;
        if (it + 1 < 16) {
            load_stage(st ^ 1, (it + 1) * 16);
            cp_wait1();
        } else {
            cp_wait0();
        }
        __syncthreads();

#pragma unroll
        for (int ks = 0; ks < 2; ks++) {
            int k = ks * 8 + tig;
            unsigned a[4][4], b[4][2];
#pragma unroll
            for (int mt = 0; mt < 4; mt++) {
                int r = warpM * 64 + mt * 16 + gid;
                a[mt][0] = __float_as_uint(As[st][r][k]);
                a[mt][1] = __float_as_uint(As[st][r + 8][k]);
                a[mt][2] = __float_as_uint(As[st][r][k + 4]);
                a[mt][3] = __float_as_uint(As[st][r + 8][k + 4]);
            }
#pragma unroll
            for (int nt = 0; nt < 4; nt++) {
                int c = warpN * 32 + nt * 8 + gid;
                b[nt][0] = __float_as_uint(Bs[st][k][c]);
                b[nt][1] = __float_as_uint(Bs[st][k + 4][c]);
            }
#pragma unroll
            for (int mt = 0; mt < 4; mt++)
#pragma unroll
                for (int nt = 0; nt < 4; nt++)
                    mma_tf32(acc[mt][nt], a[mt], b[nt]);
        }
        __syncthreads();
    }

    // epilogue: fp16 store. c0,c1 -> (row, 2*tig), c2,c3 -> (row+8, 2*tig)
#pragma unroll
    for (int mt = 0; mt < 4; mt++) {
        int r0 = blockRow + warpM * 64 + mt * 16 + gid;
#pragma unroll
        for (int nt = 0; nt < 4; nt++) {
            int c = warpN * 32 + nt * 8 + tig * 2;
            if (r0 < NN)
                *(__half2*)&g_xw_h[(size_t)r0 * 128 + c] =
                    __floats2half2_rn(acc[mt][nt][0], acc[mt][nt][1]);
            if (r0 + 8 < NN)
                *(__half2*)&g_xw_h[(size_t)(r0 + 8) * 128 + c] =
                    __floats2half2_rn(acc[mt][nt][2], acc[mt][nt][3]);
        }
    }
}

// ---------------- aggregation layer 1: warp per node, fp16 gather ----------------
__global__ void __launch_bounds__(256) k_agg1(const float* __restrict__ b1) {
    int node = blockIdx.x * 8 + (threadIdx.x >> 5);
    int lane = threadIdx.x & 31;
    if (node >= NN) return;
    int beg = g_rowstart[node];
    int end = g_rowstart[node + 1];
    float dd = g_dinv[node];

    float4 acc = make_float4(0.f, 0.f, 0.f, 0.f);
    for (int i = beg; i < end; i++) {
        int s = g_esrc[i];
        float nrm = dd * g_dinv[s];
        __half2 p[2];
        *(uint2*)p = *(const uint2*)&g_xw_h[(size_t)s * 128 + lane * 4];
        float2 f0 = __half22float2(p[0]);
        float2 f1 = __half22float2(p[1]);
        acc.x += f0.x * nrm; acc.y += f0.y * nrm;
        acc.z += f1.x * nrm; acc.w += f1.y * nrm;
    }
    float self = dd * dd;
    __half2 sp[2];
    *(uint2*)sp = *(const uint2*)&g_xw_h[(size_t)node * 128 + lane * 4];
    float2 s0 = __half22float2(sp[0]);
    float2 s1 = __half22float2(sp[1]);
    float4 bb = *(const float4*)&b1[lane * 4];
    acc.x = fmaxf(acc.x + s0.x * self + bb.x, 0.f);
    acc.y = fmaxf(acc.y + s0.y * self + bb.y, 0.f);
    acc.z = fmaxf(acc.z + s1.x * self + bb.z, 0.f);
    acc.w = fmaxf(acc.w + s1.y * self + bb.w, 0.f);
    *(float4*)&g_h[(size_t)node * 128 + lane * 4] = acc;
}

// ---------------- GEMM2: g_hw2 = g_h[N,128] @ W2[128,40] ----------------
__global__ void __launch_bounds__(256) k_gemm2(const float* __restrict__ B) {
    __shared__ float As[16][133];
    __shared__ float Bs[16][40];
    const int tid = threadIdx.x;
    const int block_row = blockIdx.x * 128;
    const int tr = (tid >> 3) * 4;
    const int tc = (tid & 7) * 5;

    float acc[4][5];
#pragma unroll
    for (int i = 0; i < 4; i++)
#pragma unroll
        for (int j = 0; j < 5; j++) acc[i][j] = 0.f;

    for (int k0 = 0; k0 < 128; k0 += 16) {
#pragma unroll
        for (int i = 0; i < 8; i++) {
            int idx = tid + i * 256;
            int m  = idx >> 4;
            int kk = idx & 15;
            int row = block_row + m;
            As[kk][m] = (row < NN) ? g_h[(size_t)row * 128 + k0 + kk] : 0.f;
        }
        for (int idx = tid; idx < 640; idx += 256) {
            int kk = idx / 40;
            int n  = idx % 40;
            Bs[kk][n] = B[(k0 + kk) * 40 + n];
        }
        __syncthreads();
#pragma unroll
        for (int kk = 0; kk < 16; kk++) {
            float a[4], b[5];
#pragma unroll
            for (int i = 0; i < 4; i++) a[i] = As[kk][tr + i];
#pragma unroll
            for (int j = 0; j < 5; j++) b[j] = Bs[kk][tc + j];
#pragma unroll
            for (int i = 0; i < 4; i++)
#pragma unroll
                for (int j = 0; j < 5; j++) acc[i][j] += a[i] * b[j];
        }
        __syncthreads();
    }
#pragma unroll
    for (int i = 0; i < 4; i++) {
        int row = block_row + tr + i;
        if (row < NN) {
#pragma unroll
            for (int j = 0; j < 5; j++) g_hw2[(size_t)row * 40 + tc + j] = acc[i][j];
        }
    }
}

// ---------------- aggregation layer 2 + bias + log_softmax, warp per node ----------------
__global__ void __launch_bounds__(256) k_agg2(const float* __restrict__ b2,
                                              float* __restrict__ out) {
    int node = blockIdx.x * 8 + (threadIdx.x >> 5);
    int lane = threadIdx.x & 31;
    if (node >= NN) return;
    int beg = g_rowstart[node];
    int end = g_rowstart[node + 1];
    float dd = g_dinv[node];
    bool active = lane < 10;   // 10 float4 chunks cover 40 cols

    float4 acc = make_float4(0.f, 0.f, 0.f, 0.f);
    for (int i = beg; i < end; i++) {
        int s = g_esrc[i];
        float nrm = dd * g_dinv[s];
        if (active) {
            float4 v = *(const float4*)&g_hw2[(size_t)s * 40 + lane * 4];
            acc.x += v.x * nrm; acc.y += v.y * nrm;
            acc.z += v.z * nrm; acc.w += v.w * nrm;
        }
    }
    if (active) {
        float self = dd * dd;
        float4 sv = *(const float4*)&g_hw2[(size_t)node * 40 + lane * 4];
        float4 bb = *(const float4*)&b2[lane * 4];
        acc.x += sv.x * self + bb.x;
        acc.y += sv.y * self + bb.y;
        acc.z += sv.z * self + bb.z;
        acc.w += sv.w * self + bb.w;
    }

    float m = active ? fmaxf(fmaxf(acc.x, acc.y), fmaxf(acc.z, acc.w)) : -INFINITY;
#pragma unroll
    for (int o = 16; o > 0; o >>= 1) m = fmaxf(m, __shfl_xor_sync(0xffffffffu, m, o));
    float s = active ? (expf(acc.x - m) + expf(acc.y - m) +
                        expf(acc.z - m) + expf(acc.w - m)) : 0.f;
#pragma unroll
    for (int o = 16; o > 0; o >>= 1) s += __shfl_xor_sync(0xffffffffu, s, o);
    float L = m + logf(s);

    if (active) {
        float4 o4;
        o4.x = acc.x - L; o4.y = acc.y - L;
        o4.z = acc.z - L; o4.w = acc.w - L;
        *(float4*)&out[(size_t)node * 40 + lane * 4] = o4;
    }
}

// ---------------- launch ----------------
extern "C" void kernel_launch(void* const* d_in, const int* in_sizes, int n_in,
                              void* d_out, int out_size) {
    const float* x  = (const float*)d_in[0];
    const int*   ei = (const int*)d_in[1];     // int32 (JAX x64 disabled)
    const float* W1 = (const float*)d_in[2];
    const float* b1 = (const float*)d_in[3];
    const float* W2 = (const float*)d_in[4];
    const float* b2 = (const float*)d_in[5];
    float* out = (float*)d_out;

    k_gemm1<<<(NN + 127) / 128, 256>>>(x, W1);   // independent of graph prep

    k_zero_deg<<<(NN + 255) / 256, 256>>>();
    k_hist<<<(EE + 255) / 256, 256>>>(ei);
    k_dinv<<<(NN + 255) / 256, 256>>>();

    k_scan1<<<NBLK, SCAN_B>>>();
    k_scan2<<<1, 128>>>();
    k_scan3<<<(NN + 255) / 256, 256>>>();
    k_fill<<<(EE + 255) / 256, 256>>>(ei);

    k_agg1<<<(NN + 7) / 8, 256>>>(b1);

    k_gemm2<<<(NN + 127) / 128, 256>>>(W2);
    k_agg2<<<(NN + 7) / 8, 256>>>(b2, out);
}

// round 7
// speedup vs baseline: 1.6929x; 1.1450x over previous
#include <cuda_runtime.h>
#include <cuda_fp16.h>
#include <math.h>

#define NN 100000
#define EE 1600000
#define SCAN_B 1024
#define NBLK ((NN + SCAN_B - 1) / SCAN_B)   // 98

// ---------------- scratch (no allocations allowed) ----------------
__device__ __align__(16) float  g_dinv[NN];
__device__ __align__(16) int    g_degi[NN];
__device__ __align__(16) int    g_rowstart[NN + 1];
__device__ __align__(16) int    g_cursor[NN];
__device__ __align__(16) int    g_bsum[256];
__device__ __align__(16) int    g_bsum2[256];
__device__ __align__(16) int    g_esrc[EE];
__device__ __align__(16) __half g_xw_h[(size_t)NN * 128]; // x @ W1 (fp16)
__device__ __align__(16) float  g_h[(size_t)NN * 128];    // relu(aggregated layer 1)
__device__ __align__(16) float  g_hw2[(size_t)NN * 40];   // relu(h) @ W2

// ---------------- degree histogram ----------------
__global__ void k_zero_deg() {
    int i = blockIdx.x * blockDim.x + threadIdx.x;
    if (i < NN) g_degi[i] = 0;
}

__global__ void k_hist(const int* __restrict__ ei) {
    int e = blockIdx.x * blockDim.x + threadIdx.x;
    if (e < EE) atomicAdd(&g_degi[ei[EE + e]], 1);
}

__global__ void k_dinv() {
    int i = blockIdx.x * blockDim.x + threadIdx.x;
    if (i < NN) g_dinv[i] = rsqrtf((float)(g_degi[i] + 1));  // +1 self loop
}

// ---------------- prefix scan (exclusive) of g_degi -> g_rowstart ----------------
__global__ void k_scan1() {
    __shared__ int sh[SCAN_B];
    int i = blockIdx.x * SCAN_B + threadIdx.x;
    int v = (i < NN) ? g_degi[i] : 0;
    sh[threadIdx.x] = v;
    __syncthreads();
    for (int o = 1; o < SCAN_B; o <<= 1) {
        int t = (threadIdx.x >= o) ? sh[threadIdx.x - o] : 0;
        __syncthreads();
        sh[threadIdx.x] += t;
        __syncthreads();
    }
    if (threadIdx.x == SCAN_B - 1) g_bsum[blockIdx.x] = sh[SCAN_B - 1];
    if (i < NN) g_rowstart[i] = sh[threadIdx.x] - v;   // exclusive
}

__global__ void k_scan2() {
    __shared__ int sh[128];
    int v = (threadIdx.x < NBLK) ? g_bsum[threadIdx.x] : 0;
    sh[threadIdx.x] = v;
    __syncthreads();
    for (int o = 1; o < 128; o <<= 1) {
        int t = (threadIdx.x >= o) ? sh[threadIdx.x - o] : 0;
        __syncthreads();
        sh[threadIdx.x] += t;
        __syncthreads();
    }
    g_bsum2[threadIdx.x] = sh[threadIdx.x] - v;        // exclusive
}

__global__ void k_scan3() {
    int i = blockIdx.x * blockDim.x + threadIdx.x;
    if (i < NN) {
        int r = g_rowstart[i] + g_bsum2[i / SCAN_B];
        g_rowstart[i] = r;
        g_cursor[i] = r;
    }
    if (i == 0) g_rowstart[NN] = EE;
}

// ---------------- counting-sort fill: CSR over dst ----------------
__global__ void k_fill(const int* __restrict__ ei) {
    int e = blockIdx.x * blockDim.x + threadIdx.x;
    if (e < EE) {
        int s = ei[e];
        int d = ei[EE + e];
        int pos = atomicAdd(&g_cursor[d], 1);
        g_esrc[pos] = s;
    }
}

// ---------------- tf32 mma + cp.async helpers ----------------
__device__ __forceinline__ void mma_tf32(float* d, const unsigned* a, const unsigned* b) {
    asm volatile(
        "mma.sync.aligned.m16n8k8.row.col.f32.tf32.tf32.f32 "
        "{%0,%1,%2,%3}, {%4,%5,%6,%7}, {%8,%9}, {%0,%1,%2,%3};"
        : "+f"(d[0]), "+f"(d[1]), "+f"(d[2]), "+f"(d[3])
        : "r"(a[0]), "r"(a[1]), "r"(a[2]), "r"(a[3]),
          "r"(b[0]), "r"(b[1]));
}

__device__ __forceinline__ void cp16(void* dst, const void* src, int src_bytes) {
    unsigned d = (unsigned)__cvta_generic_to_shared(dst);
    asm volatile("cp.async.cg.shared.global [%0], [%1], 16, %2;"
                 :: "r"(d), "l"(src), "r"(src_bytes));
}
__device__ __forceinline__ void cp_commit() { asm volatile("cp.async.commit_group;"); }
__device__ __forceinline__ void cp_wait1()  { asm volatile("cp.async.wait_group 1;"); }
__device__ __forceinline__ void cp_wait0()  { asm volatile("cp.async.wait_group 0;"); }

// ---------------- GEMM1 (tf32, double-buffered cp.async) ----------------
// g_xw_h = fp16( x[N,256] @ W1[256,128] ).  128x128 block, 8 warps (2Mx4N), BK=16.
__global__ void __launch_bounds__(256) k_gemm1(const float* __restrict__ A,
                                               const float* __restrict__ B) {
    __shared__ float As[2][128][20];   // [m][k], stride 20 -> conflict-free frags
    __shared__ float Bs[2][16][132];   // [k][n]
    const int tid   = threadIdx.x;
    const int lane  = tid & 31;
    const int gid   = lane >> 2;    // 0..7
    const int tig   = lane & 3;     // 0..3
    const int warpM = (tid >> 5) & 1;
    const int warpN = (tid >> 6);   // 0..3
    const int blockRow = blockIdx.x * 128;

    float acc[4][4][4];
#pragma unroll
    for (int mt = 0; mt < 4; mt++)
#pragma unroll
        for (int nt = 0; nt < 4; nt++)
#pragma unroll
            for (int r = 0; r < 4; r++) acc[mt][nt][r] = 0.f;

    const int ar0 = tid >> 1, ak0 = (tid & 1) * 8;
    const int bk0 = tid >> 4, bn0 = (tid & 15) * 8;

    auto load_stage = [&](int st, int k0) {
        int row = blockRow + ar0;
        int ok  = (row < NN) ? 16 : 0;
        const float* src = &A[(size_t)row * 256 + k0 + ak0];
        cp16(&As[st][ar0][ak0],     src,     ok);
        cp16(&As[st][ar0][ak0 + 4], src + 4, ok);
        const float* bs = &B[(size_t)(k0 + bk0) * 128 + bn0];
        cp16(&Bs[st][bk0][bn0],     bs,     16);
        cp16(&Bs[st][bk0][bn0 + 4], bs + 4, 16);
        cp_commit();
    };

    load_stage(0, 0);

    for (int it = 0; it < 16; it++) {
        int st = it & 1;
        if (it + 1 < 16) {
            load_stage(st ^ 1, (it + 1) * 16);
            cp_wait1();
        } else {
            cp_wait0();
        }
        __syncthreads();

#pragma unroll
        for (int ks = 0; ks < 2; ks++) {
            int k = ks * 8 + tig;
            unsigned a[4][4], b[4][2];
#pragma unroll
            for (int mt = 0; mt < 4; mt++) {
                int r = warpM * 64 + mt * 16 + gid;
                a[mt][0] = __float_as_uint(As[st][r][k]);
                a[mt][1] = __float_as_uint(As[st][r + 8][k]);
                a[mt][2] = __float_as_uint(As[st][r][k + 4]);
                a[mt][3] = __float_as_uint(As[st][r + 8][k + 4]);
            }
#pragma unroll
            for (int nt = 0; nt < 4; nt++) {
                int c = warpN * 32 + nt * 8 + gid;
                b[nt][0] = __float_as_uint(Bs[st][k][c]);
                b[nt][1] = __float_as_uint(Bs[st][k + 4][c]);
            }
#pragma unroll
            for (int mt = 0; mt < 4; mt++)
#pragma unroll
                for (int nt = 0; nt < 4; nt++)
                    mma_tf32(acc[mt][nt], a[mt], b[nt]);
        }
        __syncthreads();
    }

#pragma unroll
    for (int mt = 0; mt < 4; mt++) {
        int r0 = blockRow + warpM * 64 + mt * 16 + gid;
#pragma unroll
        for (int nt = 0; nt < 4; nt++) {
            int c = warpN * 32 + nt * 8 + tig * 2;
            if (r0 < NN)
                *(__half2*)&g_xw_h[(size_t)r0 * 128 + c] =
                    __floats2half2_rn(acc[mt][nt][0], acc[mt][nt][1]);
            if (r0 + 8 < NN)
                *(__half2*)&g_xw_h[(size_t)(r0 + 8) * 128 + c] =
                    __floats2half2_rn(acc[mt][nt][2], acc[mt][nt][3]);
        }
    }
}

// ---------------- aggregation layer 1: warp per node, fp16 gather, 2-edge ILP ----------------
__global__ void __launch_bounds__(256) k_agg1(const float* __restrict__ b1) {
    int node = blockIdx.x * 8 + (threadIdx.x >> 5);
    int lane = threadIdx.x & 31;
    if (node >= NN) return;
    int beg = g_rowstart[node];
    int end = g_rowstart[node + 1];
    float dd = g_dinv[node];

    float4 acc = make_float4(0.f, 0.f, 0.f, 0.f);
    int i = beg;
    for (; i + 1 < end; i += 2) {
        int s0 = g_esrc[i];
        int s1 = g_esrc[i + 1];
        float n0 = dd * g_dinv[s0];
        float n1 = dd * g_dinv[s1];
        __half2 p0[2], p1[2];
        *(uint2*)p0 = *(const uint2*)&g_xw_h[(size_t)s0 * 128 + lane * 4];
        *(uint2*)p1 = *(const uint2*)&g_xw_h[(size_t)s1 * 128 + lane * 4];
        float2 a0 = __half22float2(p0[0]), a1 = __half22float2(p0[1]);
        float2 c0 = __half22float2(p1[0]), c1 = __half22float2(p1[1]);
        acc.x += a0.x * n0 + c0.x * n1;
        acc.y += a0.y * n0 + c0.y * n1;
        acc.z += a1.x * n0 + c1.x * n1;
        acc.w += a1.y * n0 + c1.y * n1;
    }
    if (i < end) {
        int s = g_esrc[i];
        float nrm = dd * g_dinv[s];
        __half2 p[2];
        *(uint2*)p = *(const uint2*)&g_xw_h[(size_t)s * 128 + lane * 4];
        float2 f0 = __half22float2(p[0]);
        float2 f1 = __half22float2(p[1]);
        acc.x += f0.x * nrm; acc.y += f0.y * nrm;
        acc.z += f1.x * nrm; acc.w += f1.y * nrm;
    }
    float self = dd * dd;
    __half2 sp[2];
    *(uint2*)sp = *(const uint2*)&g_xw_h[(size_t)node * 128 + lane * 4];
    float2 s0 = __half22float2(sp[0]);
    float2 s1 = __half22float2(sp[1]);
    float4 bb = *(const float4*)&b1[lane * 4];
    acc.x = fmaxf(acc.x + s0.x * self + bb.x, 0.f);
    acc.y = fmaxf(acc.y + s0.y * self + bb.y, 0.f);
    acc.z = fmaxf(acc.z + s1.x * self + bb.z, 0.f);
    acc.w = fmaxf(acc.w + s1.y * self + bb.w, 0.f);
    *(float4*)&g_h[(size_t)node * 128 + lane * 4] = acc;
}

// ---------------- GEMM2 (tf32 MMA, double-buffered): g_hw2 = g_h @ W2[128,40] ----------------
// 128-row block, 4 warps, warp tile 32x40 (2 x m16, 5 x n8), BK=32.
__global__ void __launch_bounds__(128) k_gemm2(const float* __restrict__ B) {
    __shared__ float As[2][128][36];   // [m][k] pad 4
    __shared__ float Bs[2][32][40];    // [k][n]
    const int tid  = threadIdx.x;
    const int lane = tid & 31;
    const int gid  = lane >> 2;
    const int tig  = lane & 3;
    const int warp = tid >> 5;         // 0..3
    const int blockRow = blockIdx.x * 128;

    float acc[2][5][4];
#pragma unroll
    for (int mt = 0; mt < 2; mt++)
#pragma unroll
        for (int nt = 0; nt < 5; nt++)
#pragma unroll
            for (int r = 0; r < 4; r++) acc[mt][nt][r] = 0.f;

    auto load_stage = [&](int st, int k0) {
        // A: 128 rows x 32 k, one row per thread, 8 x cp16
        int row = blockRow + tid;
        int ok  = (row < NN) ? 16 : 0;
        const float* src = &g_h[(size_t)row * 128 + k0];
#pragma unroll
        for (int c = 0; c < 8; c++)
            cp16(&As[st][tid][c * 4], src + c * 4, ok);
        // B: 32 k x 40 n = 320 x 16B chunks
#pragma unroll
        for (int idx = tid; idx < 320; idx += 128) {
            int kk = idx / 10;
            int c4 = (idx % 10) * 4;
            cp16(&Bs[st][kk][c4], &B[(size_t)(k0 + kk) * 40 + c4], 16);
        }
        cp_commit();
    };

    load_stage(0, 0);

    for (int it = 0; it < 4; it++) {
        int st = it & 1;
        if (it + 1 < 4) {
            load_stage(st ^ 1, (it + 1) * 32);
            cp_wait1();
        } else {
            cp_wait0();
        }
        __syncthreads();

#pragma unroll
        for (int ks = 0; ks < 4; ks++) {
            int k = ks * 8 + tig;
            unsigned a[2][4], b[5][2];
#pragma unroll
            for (int mt = 0; mt < 2; mt++) {
                int r = warp * 32 + mt * 16 + gid;
                a[mt][0] = __float_as_uint(As[st][r][k]);
                a[mt][1] = __float_as_uint(As[st][r + 8][k]);
                a[mt][2] = __float_as_uint(As[st][r][k + 4]);
                a[mt][3] = __float_as_uint(As[st][r + 8][k + 4]);
            }
#pragma unroll
            for (int nt = 0; nt < 5; nt++) {
                int c = nt * 8 + gid;
                b[nt][0] = __float_as_uint(Bs[st][k][c]);
                b[nt][1] = __float_as_uint(Bs[st][k + 4][c]);
            }
#pragma unroll
            for (int mt = 0; mt < 2; mt++)
#pragma unroll
                for (int nt = 0; nt < 5; nt++)
                    mma_tf32(acc[mt][nt], a[mt], b[nt]);
        }
        __syncthreads();
    }

#pragma unroll
    for (int mt = 0; mt < 2; mt++) {
        int r0 = blockRow + warp * 32 + mt * 16 + gid;
#pragma unroll
        for (int nt = 0; nt < 5; nt++) {
            int c = nt * 8 + tig * 2;
            if (r0 < NN)
                *(float2*)&g_hw2[(size_t)r0 * 40 + c] = make_float2(acc[mt][nt][0], acc[mt][nt][1]);
            if (r0 + 8 < NN)
                *(float2*)&g_hw2[(size_t)(r0 + 8) * 40 + c] = make_float2(acc[mt][nt][2], acc[mt][nt][3]);
        }
    }
}

// ---------------- aggregation layer 2 + bias + log_softmax, warp per node ----------------
__global__ void __launch_bounds__(256) k_agg2(const float* __restrict__ b2,
                                              float* __restrict__ out) {
    int node = blockIdx.x * 8 + (threadIdx.x >> 5);
    int lane = threadIdx.x & 31;
    if (node >= NN) return;
    int beg = g_rowstart[node];
    int end = g_rowstart[node + 1];
    float dd = g_dinv[node];
    bool active = lane < 10;   // 10 float4 chunks cover 40 cols

    float4 acc = make_float4(0.f, 0.f, 0.f, 0.f);
    for (int i = beg; i < end; i++) {
        int s = g_esrc[i];
        float nrm = dd * g_dinv[s];
        if (active) {
            float4 v = *(const float4*)&g_hw2[(size_t)s * 40 + lane * 4];
            acc.x += v.x * nrm; acc.y += v.y * nrm;
            acc.z += v.z * nrm; acc.w += v.w * nrm;
        }
    }
    if (active) {
        float self = dd * dd;
        float4 sv = *(const float4*)&g_hw2[(size_t)node * 40 + lane * 4];
        float4 bb = *(const float4*)&b2[lane * 4];
        acc.x += sv.x * self + bb.x;
        acc.y += sv.y * self + bb.y;
        acc.z += sv.z * self + bb.z;
        acc.w += sv.w * self + bb.w;
    }

    float m = active ? fmaxf(fmaxf(acc.x, acc.y), fmaxf(acc.z, acc.w)) : -INFINITY;
#pragma unroll
    for (int o = 16; o > 0; o >>= 1) m = fmaxf(m, __shfl_xor_sync(0xffffffffu, m, o));
    float s = active ? (expf(acc.x - m) + expf(acc.y - m) +
                        expf(acc.z - m) + expf(acc.w - m)) : 0.f;
#pragma unroll
    for (int o = 16; o > 0; o >>= 1) s += __shfl_xor_sync(0xffffffffu, s, o);
    float L = m + logf(s);

    if (active) {
        float4 o4;
        o4.x = acc.x - L; o4.y = acc.y - L;
        o4.z = acc.z - L; o4.w = acc.w - L;
        *(float4*)&out[(size_t)node * 40 + lane * 4] = o4;
    }
}

// ---------------- launch (gemm1 at index 3 so ncu profiles it) ----------------
extern "C" void kernel_launch(void* const* d_in, const int* in_sizes, int n_in,
                              void* d_out, int out_size) {
    const float* x  = (const float*)d_in[0];
    const int*   ei = (const int*)d_in[1];     // int32 (JAX x64 disabled)
    const float* W1 = (const float*)d_in[2];
    const float* b1 = (const float*)d_in[3];
    const float* W2 = (const float*)d_in[4];
    const float* b2 = (const float*)d_in[5];
    float* out = (float*)d_out;

    k_zero_deg<<<(NN + 255) / 256, 256>>>();
    k_hist<<<(EE + 255) / 256, 256>>>(ei);
    k_dinv<<<(NN + 255) / 256, 256>>>();

    k_gemm1<<<(NN + 127) / 128, 256>>>(x, W1);   // launch index 3 -> profiled

    k_scan1<<<NBLK, SCAN_B>>>();
    k_scan2<<<1, 128>>>();
    k_scan3<<<(NN + 255) / 256, 256>>>();
    k_fill<<<(EE + 255) / 256, 256>>>(ei);

    k_agg1<<<(NN + 7) / 8, 256>>>(b1);

    k_gemm2<<<(NN + 127) / 128, 128>>>(W2);
    k_agg2<<<(NN + 7) / 8, 256>>>(b2, out);
}